// round 2
// baseline (speedup 1.0000x reference)
#include <cuda_runtime.h>
#include <cstdint>
#include <cstdio>

#define NTT  160000   // B*N flattened nodes
#define NG   5000     // graph nodes (edge indices < NG)
#define HH   128      // hidden
#define EE   80000    // edges
#define TT   12       // timesteps
#define BB   32       // batch
#define HORR 12       // horizon

typedef unsigned long long ull;

// ---------------- device scratch (static, no allocs) ----------------
__device__ float g_h[NTT * HH];          // hidden state (82 MB)
__device__ float g_P1[NG * HH];          // prop(h)
__device__ float g_P2[NG * HH];          // prop(prop(h))
__device__ float g_Px1[TT * NG * 2];     // prop(x_t) for all t
__device__ float g_Px2[TT * NG * 2];     // prop(prop(x_t))
__device__ float g_A[HH * HH];           // W2[0]-W2[2]
__device__ float g_W2c[HH * HH];         // 2*W2[2]
__device__ float g_W1cat[6 * HH];        // combined input-conv weights
__device__ float g_norm[EE];
__device__ float g_deg[NG];
__device__ int   g_src[EE];
__device__ int   g_dst[EE];
__device__ int   g_is64;

// ---------------- helpers ----------------
__device__ __forceinline__ void fma2(ull& acc, ull a, ull b) {
    asm("fma.rn.f32x2 %0, %1, %2, %0;" : "+l"(acc) : "l"(a), "l"(b));
}
__device__ __forceinline__ ull bcast2(float v) {
    ull r; asm("mov.b64 %0, {%1, %1};" : "=l"(r) : "f"(v)); return r;
}
__device__ __forceinline__ float2 ull2f2(ull u) {
    float2 f; asm("mov.b64 {%0, %1}, %2;" : "=f"(f.x), "=f"(f.y) : "l"(u)); return f;
}
__device__ __forceinline__ float sigm(float v) {
    return __fdividef(1.f, 1.f + __expf(-v));
}
__device__ __forceinline__ float tanhc(float v) {
    v = fminf(fmaxf(v, -15.f), 15.f);
    float e = __expf(2.f * v);
    return __fdividef(e - 1.f, e + 1.f);
}

// load a 16x128 weight chunk into shared (2048 floats = 512 float4; 256 thr x2)
__device__ __forceinline__ void load_w(float* ws, const float* __restrict__ Wg,
                                       int kk, int tid) {
    const float4* s = reinterpret_cast<const float4*>(Wg + (size_t)kk * HH);
    float4* d = reinterpret_cast<float4*>(ws);
    d[tid]       = s[tid];
    d[tid + 256] = s[tid + 256];
}

// thread computes 4 rows x 8 cols. acc[i][j] is a packed f32x2 (2 cols).
__device__ __forceinline__ void mma_chunk(const float* __restrict__ sA, int kb,
                                          const float* __restrict__ ws,
                                          int r0, int c0, ull acc[4][4]) {
#pragma unroll
    for (int k = 0; k < 16; k++) {
        const ulonglong2* wp = reinterpret_cast<const ulonglong2*>(ws + k * HH + c0);
        ulonglong2 w0 = wp[0], w1 = wp[1];
#pragma unroll
        for (int i = 0; i < 4; i++) {
            ull av = bcast2(sA[(r0 + i) * HH + kb + k]);
            fma2(acc[i][0], av, w0.x);
            fma2(acc[i][1], av, w0.y);
            fma2(acc[i][2], av, w1.x);
            fma2(acc[i][3], av, w1.y);
        }
    }
}

__device__ __forceinline__ void mma_chunk2(const float* __restrict__ sA, int kb,
                                           const float* __restrict__ wsa,
                                           const float* __restrict__ wsb,
                                           int r0, int c0,
                                           ull accA[4][4], ull accB[4][4]) {
#pragma unroll
    for (int k = 0; k < 16; k++) {
        const ulonglong2* wpa = reinterpret_cast<const ulonglong2*>(wsa + k * HH + c0);
        const ulonglong2* wpb = reinterpret_cast<const ulonglong2*>(wsb + k * HH + c0);
        ulonglong2 wa0 = wpa[0], wa1 = wpa[1];
        ulonglong2 wb0 = wpb[0], wb1 = wpb[1];
#pragma unroll
        for (int i = 0; i < 4; i++) {
            ull av = bcast2(sA[(r0 + i) * HH + kb + k]);
            fma2(accA[i][0], av, wa0.x);
            fma2(accA[i][1], av, wa0.y);
            fma2(accA[i][2], av, wa1.x);
            fma2(accA[i][3], av, wa1.y);
            fma2(accB[i][0], av, wb0.x);
            fma2(accB[i][1], av, wb0.y);
            fma2(accB[i][2], av, wb1.x);
            fma2(accB[i][3], av, wb1.y);
        }
    }
}

// full K=128 GEMM accumulate: acc += sA(64x128) @ Wg(128x128)
__device__ __forceinline__ void gemm128(const float* __restrict__ sA,
                                        const float* __restrict__ Wg,
                                        float* ws, int r0, int c0, int tid,
                                        ull acc[4][4]) {
    for (int kk = 0; kk < HH; kk += 16) {
        load_w(ws, Wg, kk, tid);
        __syncthreads();
        mma_chunk(sA, kk, ws, r0, c0, acc);
        __syncthreads();
    }
}

// stage a 64x128 tile from (possibly short) NG-row source, zero-pad beyond NG
__device__ __forceinline__ void stage_tile(float* dstS, const float* __restrict__ srcG,
                                           int brow, int tid) {
    float4* d4 = reinterpret_cast<float4*>(dstS);
#pragma unroll
    for (int i = 0; i < 8; i++) {
        int idx = tid + i * 256;      // 0..2047
        int r = idx >> 5, c = idx & 31;
        int row = brow + r;
        float4 v = make_float4(0.f, 0.f, 0.f, 0.f);
        if (row < NG) v = reinterpret_cast<const float4*>(srcG)[(size_t)row * 32 + c];
        d4[idx] = v;
    }
}

// ---------------- prep kernels ----------------
// JAX by default disables x64: edge_index declared int64 in the reference is
// most likely materialized as int32. Detect dtype on-device: read the first 64
// values as int64; if ALL are in [0, NG) the buffer is truly int64 (for int32
// data the odds are (1/5000)^64 ~ 0 since the high word is a random node id).
__global__ void k_detect(const void* __restrict__ ei) {
    if (threadIdx.x != 0 || blockIdx.x != 0) return;
    const long long* p64 = (const long long*)ei;
    int ok = 1;
    for (int i = 0; i < 64; i++) {
        long long v = p64[i];
        if (v < 0 || v >= NG) { ok = 0; break; }
    }
    g_is64 = ok;
}
__global__ void k_edges(const void* __restrict__ ei) {
    int e = blockIdx.x * blockDim.x + threadIdx.x;
    if (e >= EE) return;
    int s, d;
    if (g_is64) {
        const long long* p = (const long long*)ei;
        s = (int)p[e]; d = (int)p[EE + e];
    } else {
        const int* p = (const int*)ei;
        s = p[e]; d = p[EE + e];
    }
    // defensive clamp: no downstream kernel can scatter out of bounds
    s = min(max(s, 0), NG - 1);
    d = min(max(d, 0), NG - 1);
    g_src[e] = s; g_dst[e] = d;
}
__global__ void k_deg() {
    int e = blockIdx.x * blockDim.x + threadIdx.x;
    if (e < EE) atomicAdd(&g_deg[g_src[e]], 1.0f);
}
__global__ void k_norm() {
    int e = blockIdx.x * blockDim.x + threadIdx.x;
    if (e < EE) {
        float ds = g_deg[g_src[e]], dd = g_deg[g_dst[e]];
        float a = ds > 0.f ? rsqrtf(fmaxf(ds, 1.f)) : 0.f;
        float b = dd > 0.f ? rsqrtf(fmaxf(dd, 1.f)) : 0.f;
        g_norm[e] = -a * b;
    }
}
__global__ void k_wprep(const float* __restrict__ W1, const float* __restrict__ W2) {
    int i = blockIdx.x * blockDim.x + threadIdx.x;
    if (i < HH * HH) {
        float w2_2 = W2[2 * HH * HH + i];
        g_A[i] = W2[i] - w2_2;
        g_W2c[i] = 2.f * w2_2;
    }
    if (i < 6 * HH) {
        int j = i / HH, c = i % HH;
        float v;
        if (j < 2)      v = W1[j * HH + c] - W1[2 * 2 * HH + j * HH + c];
        else if (j < 4) v = W1[1 * 2 * HH + (j - 2) * HH + c];
        else            v = 2.f * W1[2 * 2 * HH + (j - 4) * HH + c];
        g_W1cat[i] = v;
    }
}
__global__ void k_xprop1(const float* __restrict__ x) {
    int idx = blockIdx.x * blockDim.x + threadIdx.x;
    if (idx >= EE * TT * 2) return;
    int c = idx & 1;
    int e = (idx >> 1) % EE;
    int t = (idx >> 1) / EE;
    float nv = g_norm[e];
    int s = g_src[e], d = g_dst[e];
    float xv = x[((size_t)t * NG + s) * 2 + c];   // batch 0 slice (src < 5000)
    atomicAdd(&g_Px1[((size_t)t * NG + d) * 2 + c], nv * xv);
}
__global__ void k_xprop2() {
    int idx = blockIdx.x * blockDim.x + threadIdx.x;
    if (idx >= EE * TT * 2) return;
    int c = idx & 1;
    int e = (idx >> 1) % EE;
    int t = (idx >> 1) / EE;
    float nv = g_norm[e];
    int s = g_src[e], d = g_dst[e];
    atomicAdd(&g_Px2[((size_t)t * NG + d) * 2 + c],
              nv * g_Px1[((size_t)t * NG + s) * 2 + c]);
}
__global__ void k_prop(const float* __restrict__ srcf, float* __restrict__ dstf) {
    int idx = blockIdx.x * blockDim.x + threadIdx.x;
    if (idx >= EE * HH) return;
    int f = idx & (HH - 1);
    int e = idx >> 7;
    atomicAdd(&dstf[(size_t)g_dst[e] * HH + f],
              g_norm[e] * srcf[(size_t)g_src[e] * HH + f]);
}

// ---------------- fused GRU step ----------------
// smem layout (floats):
//   h_s 8192 | buf_s 8192 | hc_s 8192 | rhc_s 8192 | ws0 2048 | ws1 2048 |
//   x6_s 512 | w1c_s 768 | bias_s 640   => 38784 floats = 155136 B
#define SMEM_FLOATS 38784
#define SMEM_BYTES  (SMEM_FLOATS * 4)

__global__ void __launch_bounds__(256, 1)
k_gru(const float* __restrict__ x, int t,
      const float* __restrict__ W2,
      const float* __restrict__ Wz, const float* __restrict__ Wr,
      const float* __restrict__ Wc,
      const float* __restrict__ b1, const float* __restrict__ b2,
      const float* __restrict__ bz, const float* __restrict__ br,
      const float* __restrict__ bc) {
    extern __shared__ float sm[];
    float* h_s    = sm;
    float* buf_s  = sm + 8192;
    float* hc_s   = sm + 16384;
    float* rhc_s  = sm + 24576;
    float* ws0    = sm + 32768;
    float* ws1    = sm + 34816;
    float* x6_s   = sm + 36864;
    float* w1c_s  = sm + 37376;
    float* bias_s = sm + 38144;  // [bz|br|bc|b1|b2] x128

    const int tid  = threadIdx.x;
    const int brow = blockIdx.x * 64;
    const int r0   = (tid >> 4) << 2;     // 4 rows
    const int c0   = (tid & 15) << 3;     // 8 cols

    // stage h tile (64x128)
    {
        const float4* hg = reinterpret_cast<const float4*>(g_h + (size_t)brow * HH);
        float4* hs4 = reinterpret_cast<float4*>(h_s);
#pragma unroll
        for (int i = 0; i < 8; i++) hs4[tid + i * 256] = hg[tid + i * 256];
    }
    // stage x6 (x, Px1, Px2 per row)
    if (tid < 64) {
        int row = brow + tid;
        int bb = row / NG, nl = row - bb * NG;
        const float* xp = x + ((size_t)(bb * TT + t) * NG + nl) * 2;
        x6_s[tid * 8 + 0] = xp[0];
        x6_s[tid * 8 + 1] = xp[1];
        float p10 = 0.f, p11 = 0.f, p20 = 0.f, p21 = 0.f;
        if (row < NG) {
            p10 = g_Px1[((size_t)t * NG + row) * 2 + 0];
            p11 = g_Px1[((size_t)t * NG + row) * 2 + 1];
            p20 = g_Px2[((size_t)t * NG + row) * 2 + 0];
            p21 = g_Px2[((size_t)t * NG + row) * 2 + 1];
        }
        x6_s[tid * 8 + 2] = p10; x6_s[tid * 8 + 3] = p11;
        x6_s[tid * 8 + 4] = p20; x6_s[tid * 8 + 5] = p21;
        x6_s[tid * 8 + 6] = 0.f; x6_s[tid * 8 + 7] = 0.f;
    }
    for (int i = tid; i < 6 * HH; i += 256) w1c_s[i] = g_W1cat[i];
    if (tid < 128) {
        bias_s[tid]       = bz[tid];
        bias_s[128 + tid] = br[tid];
        bias_s[256 + tid] = bc[tid];
        bias_s[384 + tid] = b1[tid];
        bias_s[512 + tid] = b2[tid];
    }
    __syncthreads();

    // ---- hc = h@A + P1@W2[1] + P2@(2 W2[2]) + b2 ----
    ull acc[4][4];
#pragma unroll
    for (int i = 0; i < 4; i++)
#pragma unroll
        for (int j = 0; j < 4; j++)
            acc[i][j] = *reinterpret_cast<const ull*>(&bias_s[512 + c0 + 2 * j]);

    gemm128(h_s, g_A, ws0, r0, c0, tid, acc);
    if (brow < NG) {
        stage_tile(buf_s, g_P1, brow, tid);
        __syncthreads();
        gemm128(buf_s, W2 + HH * HH, ws0, r0, c0, tid, acc);
        stage_tile(buf_s, g_P2, brow, tid);
        __syncthreads();
        gemm128(buf_s, g_W2c, ws0, r0, c0, tid, acc);
    }
    // write hc to smem
#pragma unroll
    for (int i = 0; i < 4; i++) {
        int off = (r0 + i) * HH + c0;
#pragma unroll
        for (int j = 0; j < 4; j++) {
            float2 v = ull2f2(acc[i][j]);
            hc_s[off + 2 * j]     = v.x;
            hc_s[off + 2 * j + 1] = v.y;
        }
    }
    // ---- ic into buf_s (6-wide input conv) ----
#pragma unroll
    for (int i = 0; i < 4; i++) {
        int r = r0 + i;
        float o[8];
#pragma unroll
        for (int q = 0; q < 8; q++) o[q] = bias_s[384 + c0 + q];
#pragma unroll
        for (int j = 0; j < 6; j++) {
            float xv = x6_s[r * 8 + j];
            const float* wr = w1c_s + j * HH + c0;
#pragma unroll
            for (int q = 0; q < 8; q++) o[q] += xv * wr[q];
        }
        float4* dp = reinterpret_cast<float4*>(&buf_s[r * HH + c0]);
        dp[0] = make_float4(o[0], o[1], o[2], o[3]);
        dp[1] = make_float4(o[4], o[5], o[6], o[7]);
    }
    __syncthreads();

    // ---- z, r : [ic|hc] @ Wz / Wr ----
    ull accZ[4][4], accR[4][4];
#pragma unroll
    for (int i = 0; i < 4; i++)
#pragma unroll
        for (int j = 0; j < 4; j++) {
            accZ[i][j] = *reinterpret_cast<const ull*>(&bias_s[c0 + 2 * j]);
            accR[i][j] = *reinterpret_cast<const ull*>(&bias_s[128 + c0 + 2 * j]);
        }
    for (int kk = 0; kk < 2 * HH; kk += 16) {
        const float* sA = (kk < HH) ? buf_s : hc_s;
        int kb = kk & (HH - 1);
        load_w(ws0, Wz + (size_t)kk * HH, 0, tid);
        load_w(ws1, Wr + (size_t)kk * HH, 0, tid);
        __syncthreads();
        mma_chunk2(sA, kb, ws0, ws1, r0, c0, accZ, accR);
        __syncthreads();
    }
    // z kept in regs, rhc into smem
    float zr[4][8];
#pragma unroll
    for (int i = 0; i < 4; i++) {
        int off = (r0 + i) * HH + c0;
        float rv[8];
#pragma unroll
        for (int j = 0; j < 4; j++) {
            float2 vz = ull2f2(accZ[i][j]);
            float2 vr = ull2f2(accR[i][j]);
            zr[i][2 * j]     = sigm(vz.x);
            zr[i][2 * j + 1] = sigm(vz.y);
            rv[2 * j]     = sigm(vr.x);
            rv[2 * j + 1] = sigm(vr.y);
        }
#pragma unroll
        for (int q = 0; q < 8; q++) rhc_s[off + q] = rv[q] * hc_s[off + q];
    }
    __syncthreads();

    // ---- h_tilde = tanh([ic | r*hc] @ Wc + bc) ----
    ull accT[4][4];
#pragma unroll
    for (int i = 0; i < 4; i++)
#pragma unroll
        for (int j = 0; j < 4; j++)
            accT[i][j] = *reinterpret_cast<const ull*>(&bias_s[256 + c0 + 2 * j]);
    for (int kk = 0; kk < 2 * HH; kk += 16) {
        const float* sA = (kk < HH) ? buf_s : rhc_s;
        int kb = kk & (HH - 1);
        load_w(ws0, Wc + (size_t)kk * HH, 0, tid);
        __syncthreads();
        mma_chunk(sA, kb, ws0, r0, c0, accT);
        __syncthreads();
    }
    // ---- h_new = z*h + (1-z)*h_tilde ----
#pragma unroll
    for (int i = 0; i < 4; i++) {
        int off = (r0 + i) * HH + c0;
        float o[8];
#pragma unroll
        for (int j = 0; j < 4; j++) {
            float2 vt = ull2f2(accT[i][j]);
            float t0 = tanhc(vt.x), t1 = tanhc(vt.y);
            float z0 = zr[i][2 * j], z1 = zr[i][2 * j + 1];
            float h0 = h_s[off + 2 * j], h1 = h_s[off + 2 * j + 1];
            o[2 * j]     = z0 * h0 + (1.f - z0) * t0;
            o[2 * j + 1] = z1 * h1 + (1.f - z1) * t1;
        }
        float4* gp = reinterpret_cast<float4*>(&g_h[(size_t)(brow + r0 + i) * HH + c0]);
        gp[0] = make_float4(o[0], o[1], o[2], o[3]);
        gp[1] = make_float4(o[4], o[5], o[6], o[7]);
    }
}

// ---------------- output projection ----------------
__global__ void k_out(const float* __restrict__ Wo, const float* __restrict__ bo,
                      float* __restrict__ out) {
    int gid = blockIdx.x * blockDim.x + threadIdx.x;
    if (gid >= NTT * HORR) return;
    int hor = gid % HORR;
    int n = gid / HORR;
    const float* hr = g_h + (size_t)n * HH;
    float acc = bo[hor];
#pragma unroll 8
    for (int k = 0; k < HH; k++) acc += hr[k] * Wo[k * HORR + hor];
    int bb = n / NG, nl = n - bb * NG;
    out[((size_t)bb * HORR + hor) * NG + nl] = acc;
}

// ---------------- launch ----------------
extern "C" void kernel_launch(void* const* d_in, const int* in_sizes, int n_in,
                              void* d_out, int out_size) {
    const float* x  = (const float*)d_in[0];
    const void* ei  = d_in[1];
    const float* W1 = (const float*)d_in[2];
    const float* b1 = (const float*)d_in[3];
    const float* W2 = (const float*)d_in[4];
    const float* b2 = (const float*)d_in[5];
    const float* Wz = (const float*)d_in[6];
    const float* bz = (const float*)d_in[7];
    const float* Wr = (const float*)d_in[8];
    const float* br = (const float*)d_in[9];
    const float* Wc = (const float*)d_in[10];
    const float* bc = (const float*)d_in[11];
    const float* Wo = (const float*)d_in[12];
    const float* bo = (const float*)d_in[13];
    float* out = (float*)d_out;

    cudaFuncSetAttribute(k_gru, cudaFuncAttributeMaxDynamicSharedMemorySize, SMEM_BYTES);

    void *p_h, *p_P1, *p_P2, *p_Px1, *p_Px2, *p_deg;
    cudaGetSymbolAddress(&p_h, g_h);
    cudaGetSymbolAddress(&p_P1, g_P1);
    cudaGetSymbolAddress(&p_P2, g_P2);
    cudaGetSymbolAddress(&p_Px1, g_Px1);
    cudaGetSymbolAddress(&p_Px2, g_Px2);
    cudaGetSymbolAddress(&p_deg, g_deg);

    cudaMemsetAsync(p_h, 0, sizeof(float) * (size_t)NTT * HH);
    cudaMemsetAsync(p_deg, 0, sizeof(float) * NG);
    cudaMemsetAsync(p_Px1, 0, sizeof(float) * TT * NG * 2);
    cudaMemsetAsync(p_Px2, 0, sizeof(float) * TT * NG * 2);

    const int TPB = 256;
    k_detect<<<1, 1>>>(ei);
    k_edges<<<(EE + TPB - 1) / TPB, TPB>>>(ei);
    k_deg<<<(EE + TPB - 1) / TPB, TPB>>>();
    k_norm<<<(EE + TPB - 1) / TPB, TPB>>>();
    k_wprep<<<(HH * HH + TPB - 1) / TPB, TPB>>>(W1, W2);
    k_xprop1<<<(EE * TT * 2 + TPB - 1) / TPB, TPB>>>(x);
    k_xprop2<<<(EE * TT * 2 + TPB - 1) / TPB, TPB>>>();

    for (int t = 0; t < TT; t++) {
        cudaMemsetAsync(p_P1, 0, sizeof(float) * NG * HH);
        cudaMemsetAsync(p_P2, 0, sizeof(float) * NG * HH);
        k_prop<<<(EE * HH + TPB - 1) / TPB, TPB>>>((const float*)p_h, (float*)p_P1);
        k_prop<<<(EE * HH + TPB - 1) / TPB, TPB>>>((const float*)p_P1, (float*)p_P2);
        k_gru<<<NTT / 64, TPB, SMEM_BYTES>>>(x, t, W2, Wz, Wr, Wc,
                                             b1, b2, bz, br, bc);
    }
    k_out<<<(NTT * HORR + TPB - 1) / TPB, TPB>>>(Wo, bo, out);
}

// round 5
// speedup vs baseline: 1.6977x; 1.6977x over previous
#include <cuda_runtime.h>
#include <cstdint>
#include <cstdio>

#define NTT  160000   // B*N flattened nodes
#define NG   5000     // graph nodes (edge indices < NG)
#define HH   128      // hidden
#define EE   80000    // edges
#define TT   12       // timesteps
#define BB   32       // batch
#define HORR 12       // horizon

typedef unsigned long long ull;

// ---------------- device scratch (static, no allocs) ----------------
__device__ float g_h[NTT * HH];          // hidden state (82 MB)
__device__ float g_P1[NG * HH];          // prop(h)
__device__ float g_P2[NG * HH];          // prop(prop(h))
__device__ float g_Px1[TT * NG * 2];     // prop(x_t) for all t
__device__ float g_Px2[TT * NG * 2];     // prop(prop(x_t))
__device__ float g_A[HH * HH];           // W2[0]-W2[2]
__device__ float g_W2c[HH * HH];         // 2*W2[2]
__device__ float g_W1cat[6 * HH];        // combined input-conv weights
__device__ float g_Wf[3 * 6 * HH];       // W1cat @ {Wz,Wr,Wc}_top  (rank-6 fold)
__device__ float g_bias2[3 * HH];        // b1@{Wz,Wr,Wc}_top + {bz,br,bc}
__device__ float g_norm[EE];
__device__ float g_deg[NG];
__device__ int   g_src[EE];
__device__ int   g_dst[EE];
__device__ int   g_is64;
// CSR by dst
__device__ int   g_cnt[NG];
__device__ int   g_fill[NG];
__device__ int   g_rowptr[NG + 1];
__device__ int   g_csrc[EE];
__device__ float g_cnorm[EE];

// ---------------- helpers ----------------
__device__ __forceinline__ void fma2(ull& acc, ull a, ull b) {
    asm("fma.rn.f32x2 %0, %1, %2, %0;" : "+l"(acc) : "l"(a), "l"(b));
}
__device__ __forceinline__ ull bcast2(float v) {
    ull r; asm("mov.b64 %0, {%1, %1};" : "=l"(r) : "f"(v)); return r;
}
__device__ __forceinline__ ull pack2(float a, float b) {
    ull r; asm("mov.b64 %0, {%1, %2};" : "=l"(r) : "f"(a), "f"(b)); return r;
}
__device__ __forceinline__ float2 ull2f2(ull u) {
    float2 f; asm("mov.b64 {%0, %1}, %2;" : "=f"(f.x), "=f"(f.y) : "l"(u)); return f;
}
__device__ __forceinline__ float sigm(float v) {
    return __fdividef(1.f, 1.f + __expf(-v));
}
__device__ __forceinline__ float tanhc(float v) {
    v = fminf(fmaxf(v, -15.f), 15.f);
    float e = __expf(2.f * v);
    return __fdividef(e - 1.f, e + 1.f);
}

// load a 16x128 weight chunk into shared (2048 floats = 512 float4, 512 thr)
__device__ __forceinline__ void load_w(float* ws, const float* __restrict__ Wg,
                                       int tid) {
    reinterpret_cast<float4*>(ws)[tid] = reinterpret_cast<const float4*>(Wg)[tid];
}

// thread computes 4 rows x 8 cols. acc[i][j] is a packed f32x2 (2 cols).
__device__ __forceinline__ void mma_chunk(const float* __restrict__ sA, int kb,
                                          const float* __restrict__ ws,
                                          int r0, int c0, ull acc[4][4]) {
#pragma unroll
    for (int k = 0; k < 16; k++) {
        const ulonglong2* wp = reinterpret_cast<const ulonglong2*>(ws + k * HH + c0);
        ulonglong2 w0 = wp[0], w1 = wp[1];
#pragma unroll
        for (int i = 0; i < 4; i++) {
            ull av = bcast2(sA[(r0 + i) * HH + kb + k]);
            fma2(acc[i][0], av, w0.x);
            fma2(acc[i][1], av, w0.y);
            fma2(acc[i][2], av, w1.x);
            fma2(acc[i][3], av, w1.y);
        }
    }
}

__device__ __forceinline__ void mma_chunk2(const float* __restrict__ sA, int kb,
                                           const float* __restrict__ wsa,
                                           const float* __restrict__ wsb,
                                           int r0, int c0,
                                           ull accA[4][4], ull accB[4][4]) {
#pragma unroll
    for (int k = 0; k < 16; k++) {
        const ulonglong2* wpa = reinterpret_cast<const ulonglong2*>(wsa + k * HH + c0);
        const ulonglong2* wpb = reinterpret_cast<const ulonglong2*>(wsb + k * HH + c0);
        ulonglong2 wa0 = wpa[0], wa1 = wpa[1];
        ulonglong2 wb0 = wpb[0], wb1 = wpb[1];
#pragma unroll
        for (int i = 0; i < 4; i++) {
            ull av = bcast2(sA[(r0 + i) * HH + kb + k]);
            fma2(accA[i][0], av, wa0.x);
            fma2(accA[i][1], av, wa0.y);
            fma2(accA[i][2], av, wa1.x);
            fma2(accA[i][3], av, wa1.y);
            fma2(accB[i][0], av, wb0.x);
            fma2(accB[i][1], av, wb0.y);
            fma2(accB[i][2], av, wb1.x);
            fma2(accB[i][3], av, wb1.y);
        }
    }
}

// full K=128 GEMM accumulate: acc += sA(128x128) @ Wg(128x128)
__device__ __forceinline__ void gemm128(const float* __restrict__ sA,
                                        const float* __restrict__ Wg,
                                        float* ws, int r0, int c0, int tid,
                                        ull acc[4][4]) {
    for (int kk = 0; kk < HH; kk += 16) {
        load_w(ws, Wg + kk * HH, tid);
        __syncthreads();
        mma_chunk(sA, kk, ws, r0, c0, acc);
        __syncthreads();
    }
}

// stage a 128x128 tile from (possibly short) NG-row source, zero-pad beyond NG
__device__ __forceinline__ void stage_tile(float* dstS, const float* __restrict__ srcG,
                                           int brow, int tid) {
    float4* d4 = reinterpret_cast<float4*>(dstS);
#pragma unroll
    for (int i = 0; i < 8; i++) {
        int idx = tid + i * 512;      // 0..4095
        int r = idx >> 5, c = idx & 31;
        int row = brow + r;
        float4 v = make_float4(0.f, 0.f, 0.f, 0.f);
        if (row < NG) v = reinterpret_cast<const float4*>(srcG)[(size_t)row * 32 + c];
        d4[idx] = v;
    }
}

// ---------------- prep kernels ----------------
__global__ void k_detect(const void* __restrict__ ei) {
    if (threadIdx.x != 0 || blockIdx.x != 0) return;
    const long long* p64 = (const long long*)ei;
    int ok = 1;
    for (int i = 0; i < 64; i++) {
        long long v = p64[i];
        if (v < 0 || v >= NG) { ok = 0; break; }
    }
    g_is64 = ok;
}
__global__ void k_edges(const void* __restrict__ ei) {
    int e = blockIdx.x * blockDim.x + threadIdx.x;
    if (e >= EE) return;
    int s, d;
    if (g_is64) {
        const long long* p = (const long long*)ei;
        s = (int)p[e]; d = (int)p[EE + e];
    } else {
        const int* p = (const int*)ei;
        s = p[e]; d = p[EE + e];
    }
    s = min(max(s, 0), NG - 1);
    d = min(max(d, 0), NG - 1);
    g_src[e] = s; g_dst[e] = d;
}
__global__ void k_deg() {
    int e = blockIdx.x * blockDim.x + threadIdx.x;
    if (e < EE) {
        atomicAdd(&g_deg[g_src[e]], 1.0f);
        atomicAdd(&g_cnt[g_dst[e]], 1);
    }
}
__global__ void k_norm() {
    int e = blockIdx.x * blockDim.x + threadIdx.x;
    if (e < EE) {
        float ds = g_deg[g_src[e]], dd = g_deg[g_dst[e]];
        float a = ds > 0.f ? rsqrtf(fmaxf(ds, 1.f)) : 0.f;
        float b = dd > 0.f ? rsqrtf(fmaxf(dd, 1.f)) : 0.f;
        g_norm[e] = -a * b;
    }
}
// 1-block prefix sum of g_cnt -> g_rowptr (chunk-per-thread + serial partials)
#define SCAN_T 256
#define SCAN_C ((NG + SCAN_T - 1) / SCAN_T)
__global__ void k_scan() {
    __shared__ int part[SCAN_T];
    __shared__ int offs[SCAN_T];
    int tid = threadIdx.x;
    int base = tid * SCAN_C;
    int s = 0;
    for (int i = 0; i < SCAN_C; i++)
        if (base + i < NG) s += g_cnt[base + i];
    part[tid] = s;
    __syncthreads();
    if (tid == 0) {
        int run = 0;
        for (int i = 0; i < SCAN_T; i++) { offs[i] = run; run += part[i]; }
        g_rowptr[NG] = run;
    }
    __syncthreads();
    int run = offs[tid];
    for (int i = 0; i < SCAN_C; i++) {
        if (base + i < NG) { g_rowptr[base + i] = run; run += g_cnt[base + i]; }
    }
}
__global__ void k_fill() {
    int e = blockIdx.x * blockDim.x + threadIdx.x;
    if (e >= EE) return;
    int d = g_dst[e];
    int pos = g_rowptr[d] + atomicAdd(&g_fill[d], 1);
    g_csrc[pos] = g_src[e];
    g_cnorm[pos] = g_norm[e];
}
__global__ void k_wprep(const float* __restrict__ W1, const float* __restrict__ W2) {
    int i = blockIdx.x * blockDim.x + threadIdx.x;
    if (i < HH * HH) {
        float w2_2 = W2[2 * HH * HH + i];
        g_A[i] = W2[i] - w2_2;
        g_W2c[i] = 2.f * w2_2;
    }
    if (i < 6 * HH) {
        int j = i / HH, c = i % HH;
        float v;
        if (j < 2)      v = W1[j * HH + c] - W1[2 * 2 * HH + j * HH + c];
        else if (j < 4) v = W1[1 * 2 * HH + (j - 2) * HH + c];
        else            v = 2.f * W1[2 * 2 * HH + (j - 4) * HH + c];
        g_W1cat[i] = v;
    }
}
// rank-6 fold: g_Wf[g][j][c] = sum_k W1cat[j][k] * Wg_top[k][c]
__global__ void k_wfold(const float* __restrict__ Wz, const float* __restrict__ Wr,
                        const float* __restrict__ Wc,
                        const float* __restrict__ b1,
                        const float* __restrict__ bz, const float* __restrict__ br,
                        const float* __restrict__ bc) {
    int idx = blockIdx.x * blockDim.x + threadIdx.x;
    if (idx < 3 * 6 * HH) {
        int g = idx / (6 * HH);
        int j = (idx % (6 * HH)) / HH;
        int c = idx % HH;
        const float* Wg = (g == 0) ? Wz : (g == 1) ? Wr : Wc;
        float s = 0.f;
        for (int k = 0; k < HH; k++) s += g_W1cat[j * HH + k] * Wg[k * HH + c];
        g_Wf[idx] = s;
    }
    if (idx < 3 * HH) {
        int g = idx / HH, c = idx % HH;
        const float* Wg = (g == 0) ? Wz : (g == 1) ? Wr : Wc;
        const float* bg = (g == 0) ? bz : (g == 1) ? br : bc;
        float s = bg[c];
        for (int k = 0; k < HH; k++) s += b1[k] * Wg[k * HH + c];
        g_bias2[idx] = s;
    }
}
__global__ void k_xprop1(const float* __restrict__ x) {
    int idx = blockIdx.x * blockDim.x + threadIdx.x;
    if (idx >= EE * TT * 2) return;
    int c = idx & 1;
    int e = (idx >> 1) % EE;
    int t = (idx >> 1) / EE;
    float nv = g_norm[e];
    int s = g_src[e], d = g_dst[e];
    float xv = x[((size_t)t * NG + s) * 2 + c];   // batch 0 slice (src < 5000)
    atomicAdd(&g_Px1[((size_t)t * NG + d) * 2 + c], nv * xv);
}
__global__ void k_xprop2() {
    int idx = blockIdx.x * blockDim.x + threadIdx.x;
    if (idx >= EE * TT * 2) return;
    int c = idx & 1;
    int e = (idx >> 1) % EE;
    int t = (idx >> 1) / EE;
    float nv = g_norm[e];
    int s = g_src[e], d = g_dst[e];
    atomicAdd(&g_Px2[((size_t)t * NG + d) * 2 + c],
              nv * g_Px1[((size_t)t * NG + s) * 2 + c]);
}
// CSR gather prop: one warp per dst row, no atomics, writes full row (no memset)
__global__ void k_prop_csr(const float* __restrict__ srcf, float* __restrict__ dstf) {
    int warp = (blockIdx.x * blockDim.x + threadIdx.x) >> 5;
    int lane = threadIdx.x & 31;
    if (warp >= NG) return;
    int beg = g_rowptr[warp], end = g_rowptr[warp + 1];
    float4 acc = make_float4(0.f, 0.f, 0.f, 0.f);
    for (int p = beg; p < end; p++) {
        int s = g_csrc[p];
        float nv = g_cnorm[p];
        float4 v = reinterpret_cast<const float4*>(srcf)[(size_t)s * 32 + lane];
        acc.x += nv * v.x; acc.y += nv * v.y;
        acc.z += nv * v.z; acc.w += nv * v.w;
    }
    reinterpret_cast<float4*>(dstf)[(size_t)warp * 32 + lane] = acc;
}

// ---------------- fused GRU step (128 rows / 512 threads) ----------------
// smem (floats): h_s 16384 | hc_s 16384 | rhc_s 16384 | ws0 2048 | ws1 2048 |
//                x6_s 1024 | wf_s 2304 | bias_s 512   => 57088 floats = 228352 B
#define SMEM_FLOATS 57088
#define SMEM_BYTES  (SMEM_FLOATS * 4)

__global__ void __launch_bounds__(512, 1)
k_gru(const float* __restrict__ x, int t,
      const float* __restrict__ W2,
      const float* __restrict__ Wz, const float* __restrict__ Wr,
      const float* __restrict__ Wc,
      const float* __restrict__ b2) {
    extern __shared__ float sm[];
    float* h_s    = sm;
    float* hc_s   = sm + 16384;
    float* rhc_s  = sm + 32768;   // also reused as P-staging buffer in pass1
    float* ws0    = sm + 49152;
    float* ws1    = sm + 51200;
    float* x6_s   = sm + 53248;   // 128 rows x 8
    float* wf_s   = sm + 54272;   // 3 x 6 x 128
    float* bias_s = sm + 56576;   // [bz2 | br2 | bc2 | b2] x128

    const int tid  = threadIdx.x;
    const int brow = blockIdx.x * 128;
    const int r0   = (tid >> 4) << 2;     // 4 rows (0..124)
    const int c0   = (tid & 15) << 3;     // 8 cols

    // stage h tile (128x128)
    {
        const float4* hg = reinterpret_cast<const float4*>(g_h + (size_t)brow * HH);
        float4* hs4 = reinterpret_cast<float4*>(h_s);
#pragma unroll
        for (int i = 0; i < 8; i++) hs4[tid + i * 512] = hg[tid + i * 512];
    }
    // stage x6 (x, Px1, Px2 per row)
    if (tid < 128) {
        int row = brow + tid;
        int bb = row / NG, nl = row - bb * NG;
        const float* xp = x + ((size_t)(bb * TT + t) * NG + nl) * 2;
        x6_s[tid * 8 + 0] = xp[0];
        x6_s[tid * 8 + 1] = xp[1];
        float p10 = 0.f, p11 = 0.f, p20 = 0.f, p21 = 0.f;
        if (row < NG) {
            p10 = g_Px1[((size_t)t * NG + row) * 2 + 0];
            p11 = g_Px1[((size_t)t * NG + row) * 2 + 1];
            p20 = g_Px2[((size_t)t * NG + row) * 2 + 0];
            p21 = g_Px2[((size_t)t * NG + row) * 2 + 1];
        }
        x6_s[tid * 8 + 2] = p10; x6_s[tid * 8 + 3] = p11;
        x6_s[tid * 8 + 4] = p20; x6_s[tid * 8 + 5] = p21;
        x6_s[tid * 8 + 6] = 0.f; x6_s[tid * 8 + 7] = 0.f;
    }
    for (int i = tid; i < 3 * 6 * HH; i += 512) wf_s[i] = g_Wf[i];
    if (tid < 128) {
        bias_s[tid]       = g_bias2[tid];            // bz2
        bias_s[128 + tid] = g_bias2[128 + tid];      // br2
        bias_s[256 + tid] = g_bias2[256 + tid];      // bc2
        bias_s[384 + tid] = b2[tid];                 // b2
    }
    __syncthreads();

    // ---- pass1: hc = h@A + b2  (+ graph rows: P1@W2[1] + P2@(2W2[2])) ----
    ull acc[4][4];
#pragma unroll
    for (int i = 0; i < 4; i++)
#pragma unroll
        for (int j = 0; j < 4; j++)
            acc[i][j] = *reinterpret_cast<const ull*>(&bias_s[384 + c0 + 2 * j]);

    gemm128(h_s, g_A, ws0, r0, c0, tid, acc);
    if (brow < NG) {
        stage_tile(rhc_s, g_P1, brow, tid);
        __syncthreads();
        gemm128(rhc_s, W2 + HH * HH, ws0, r0, c0, tid, acc);
        stage_tile(rhc_s, g_P2, brow, tid);
        __syncthreads();
        gemm128(rhc_s, g_W2c, ws0, r0, c0, tid, acc);
    }
#pragma unroll
    for (int i = 0; i < 4; i++) {
        int off = (r0 + i) * HH + c0;
#pragma unroll
        for (int j = 0; j < 4; j++) {
            float2 v = ull2f2(acc[i][j]);
            hc_s[off + 2 * j]     = v.x;
            hc_s[off + 2 * j + 1] = v.y;
        }
    }

    // ---- pass2: z, r = sigm(cz/cr + hc @ W{z,r}_bot) ----
    ull accZ[4][4], accR[4][4];
#pragma unroll
    for (int i = 0; i < 4; i++) {
        const float* xr = &x6_s[(r0 + i) * 8];
        float oz[8], orr[8];
#pragma unroll
        for (int q = 0; q < 8; q++) {
            oz[q]  = bias_s[c0 + q];
            orr[q] = bias_s[128 + c0 + q];
        }
#pragma unroll
        for (int j = 0; j < 6; j++) {
            float xv = xr[j];
            const float* wz = wf_s + j * HH + c0;
            const float* wr = wf_s + 768 + j * HH + c0;
#pragma unroll
            for (int q = 0; q < 8; q++) { oz[q] += xv * wz[q]; orr[q] += xv * wr[q]; }
        }
#pragma unroll
        for (int j = 0; j < 4; j++) {
            accZ[i][j] = pack2(oz[2 * j], oz[2 * j + 1]);
            accR[i][j] = pack2(orr[2 * j], orr[2 * j + 1]);
        }
    }
    for (int kk = 0; kk < HH; kk += 16) {
        load_w(ws0, Wz + (HH + kk) * HH, tid);
        load_w(ws1, Wr + (HH + kk) * HH, tid);
        __syncthreads();
        mma_chunk2(hc_s, kk, ws0, ws1, r0, c0, accZ, accR);
        __syncthreads();
    }
    // rhc = sigm(r) * hc (own elements); park z = sigm(accZ) in hc_s slots
#pragma unroll
    for (int i = 0; i < 4; i++) {
        int off = (r0 + i) * HH + c0;
#pragma unroll
        for (int j = 0; j < 4; j++) {
            float2 vz = ull2f2(accZ[i][j]);
            float2 vr = ull2f2(accR[i][j]);
            float r0v = sigm(vr.x), r1v = sigm(vr.y);
            float hc0 = hc_s[off + 2 * j], hc1 = hc_s[off + 2 * j + 1];
            rhc_s[off + 2 * j]     = r0v * hc0;
            rhc_s[off + 2 * j + 1] = r1v * hc1;
            hc_s[off + 2 * j]      = sigm(vz.x);   // z stored in place
            hc_s[off + 2 * j + 1]  = sigm(vz.y);
        }
    }

    // ---- pass3: h_tilde = tanh(cc + rhc @ Wc_bot); h_new = z*h + (1-z)*h_t ----
    ull accT[4][4];
#pragma unroll
    for (int i = 0; i < 4; i++) {
        const float* xr = &x6_s[(r0 + i) * 8];
        float oc[8];
#pragma unroll
        for (int q = 0; q < 8; q++) oc[q] = bias_s[256 + c0 + q];
#pragma unroll
        for (int j = 0; j < 6; j++) {
            float xv = xr[j];
            const float* wc = wf_s + 1536 + j * HH + c0;
#pragma unroll
            for (int q = 0; q < 8; q++) oc[q] += xv * wc[q];
        }
#pragma unroll
        for (int j = 0; j < 4; j++) accT[i][j] = pack2(oc[2 * j], oc[2 * j + 1]);
    }
    gemm128(rhc_s, Wc + HH * HH, ws0, r0, c0, tid, accT);
#pragma unroll
    for (int i = 0; i < 4; i++) {
        int off = (r0 + i) * HH + c0;
        float o[8];
#pragma unroll
        for (int j = 0; j < 4; j++) {
            float2 vt = ull2f2(accT[i][j]);
            float t0 = tanhc(vt.x), t1 = tanhc(vt.y);
            float z0 = hc_s[off + 2 * j], z1 = hc_s[off + 2 * j + 1];
            float h0 = h_s[off + 2 * j], h1 = h_s[off + 2 * j + 1];
            o[2 * j]     = z0 * h0 + (1.f - z0) * t0;
            o[2 * j + 1] = z1 * h1 + (1.f - z1) * t1;
        }
        float4* gp = reinterpret_cast<float4*>(&g_h[(size_t)(brow + r0 + i) * HH + c0]);
        gp[0] = make_float4(o[0], o[1], o[2], o[3]);
        gp[1] = make_float4(o[4], o[5], o[6], o[7]);
    }
}

// ---------------- output projection ----------------
__global__ void k_out(const float* __restrict__ Wo, const float* __restrict__ bo,
                      float* __restrict__ out) {
    int gid = blockIdx.x * blockDim.x + threadIdx.x;
    if (gid >= NTT * HORR) return;
    int hor = gid % HORR;
    int n = gid / HORR;
    const float* hr = g_h + (size_t)n * HH;
    float acc = bo[hor];
#pragma unroll 8
    for (int k = 0; k < HH; k++) acc += hr[k] * Wo[k * HORR + hor];
    int bb = n / NG, nl = n - bb * NG;
    out[((size_t)bb * HORR + hor) * NG + nl] = acc;
}

// ---------------- launch ----------------
extern "C" void kernel_launch(void* const* d_in, const int* in_sizes, int n_in,
                              void* d_out, int out_size) {
    const float* x  = (const float*)d_in[0];
    const void* ei  = d_in[1];
    const float* W1 = (const float*)d_in[2];
    const float* b1 = (const float*)d_in[3];
    const float* W2 = (const float*)d_in[4];
    const float* b2 = (const float*)d_in[5];
    const float* Wz = (const float*)d_in[6];
    const float* bz = (const float*)d_in[7];
    const float* Wr = (const float*)d_in[8];
    const float* br = (const float*)d_in[9];
    const float* Wc = (const float*)d_in[10];
    const float* bc = (const float*)d_in[11];
    const float* Wo = (const float*)d_in[12];
    const float* bo = (const float*)d_in[13];
    float* out = (float*)d_out;

    cudaFuncSetAttribute(k_gru, cudaFuncAttributeMaxDynamicSharedMemorySize, SMEM_BYTES);

    void *p_h, *p_P1, *p_P2, *p_Px1, *p_Px2, *p_deg, *p_cnt, *p_fill;
    cudaGetSymbolAddress(&p_h, g_h);
    cudaGetSymbolAddress(&p_P1, g_P1);
    cudaGetSymbolAddress(&p_P2, g_P2);
    cudaGetSymbolAddress(&p_Px1, g_Px1);
    cudaGetSymbolAddress(&p_Px2, g_Px2);
    cudaGetSymbolAddress(&p_deg, g_deg);
    cudaGetSymbolAddress(&p_cnt, g_cnt);
    cudaGetSymbolAddress(&p_fill, g_fill);

    cudaMemsetAsync(p_h, 0, sizeof(float) * (size_t)NTT * HH);
    cudaMemsetAsync(p_deg, 0, sizeof(float) * NG);
    cudaMemsetAsync(p_cnt, 0, sizeof(int) * NG);
    cudaMemsetAsync(p_fill, 0, sizeof(int) * NG);
    cudaMemsetAsync(p_Px1, 0, sizeof(float) * TT * NG * 2);
    cudaMemsetAsync(p_Px2, 0, sizeof(float) * TT * NG * 2);

    const int TPB = 256;
    k_detect<<<1, 1>>>(ei);
    k_edges<<<(EE + TPB - 1) / TPB, TPB>>>(ei);
    k_deg<<<(EE + TPB - 1) / TPB, TPB>>>();
    k_norm<<<(EE + TPB - 1) / TPB, TPB>>>();
    k_scan<<<1, SCAN_T>>>();
    k_fill<<<(EE + TPB - 1) / TPB, TPB>>>();
    k_wprep<<<(HH * HH + TPB - 1) / TPB, TPB>>>(W1, W2);
    k_wfold<<<(3 * 6 * HH + TPB - 1) / TPB, TPB>>>(Wz, Wr, Wc, b1, bz, br, bc);
    k_xprop1<<<(EE * TT * 2 + TPB - 1) / TPB, TPB>>>(x);
    k_xprop2<<<(EE * TT * 2 + TPB - 1) / TPB, TPB>>>();

    const int PROP_B = (NG * 32 + TPB - 1) / TPB;
    for (int t = 0; t < TT; t++) {
        k_prop_csr<<<PROP_B, TPB>>>((const float*)p_h, (float*)p_P1);
        k_prop_csr<<<PROP_B, TPB>>>((const float*)p_P1, (float*)p_P2);
        k_gru<<<NTT / 128, 512, SMEM_BYTES>>>(x, t, W2, Wz, Wr, Wc, b2);
    }
    k_out<<<(NTT * HORR + TPB - 1) / TPB, TPB>>>(Wo, bo, out);
}